// round 6
// baseline (speedup 1.0000x reference)
#include <cuda_runtime.h>
#include <cfloat>

#define OUTD 5
#define NVOX 125          // OUTD^3
#define NB 2
#define NP 8192
#define NR 64
#define NC 64
#define NT 1024           // threads per CTA
#define PPT (NP / NT)     // 8 points per thread
#define LCAP 1024         // inside-point list capacity (expected ~42)

// transposed feature scratch [B][P][C], 4 MB
__device__ float g_tf[NB * NP * NC];

// float atomic max on shared memory via int punning
__device__ __forceinline__ void atomicMaxFloat(float* addr, float value) {
    if (value >= 0.0f) {
        atomicMax((int*)addr, __float_as_int(value));
    } else {
        atomicMin((unsigned int*)addr, __float_as_uint(value));
    }
}

// ---------------- transpose: feats [B,C,P] -> g_tf [B,P,C] ----------------
// grid: (P/32, C/32, B), block 256 (32x8), each thread does 4 rows of the tile
__global__ void __launch_bounds__(256)
transpose_kernel(const float* __restrict__ feats)
{
    __shared__ float tile[32][33];
    const int b  = blockIdx.z;
    const int p0 = blockIdx.x * 32;
    const int c0 = blockIdx.y * 32;
    const int tx = threadIdx.x & 31;
    const int ty = threadIdx.x >> 5;       // 0..7

    const float* src = feats + ((size_t)b * NC + c0) * NP + p0;
    #pragma unroll
    for (int j = 0; j < 4; j++) {
        const int c = ty + j * 8;
        tile[c][tx] = src[(size_t)c * NP + tx];   // coalesced in p
    }
    __syncthreads();
    float* dst = g_tf + ((size_t)b * NP + p0) * NC + c0;
    #pragma unroll
    for (int j = 0; j < 4; j++) {
        const int p = ty + j * 8;
        dst[(size_t)p * NC + tx] = tile[tx][p];   // coalesced in c
    }
}

// ---------------- main: classify + pooled max + writeout ----------------
__global__ void __launch_bounds__(NT)
roipool3d_kernel(const float* __restrict__ pts,    // [B,P,3]
                 const float* __restrict__ rois,   // [B,R,7]
                 float* __restrict__ out)          // [B*R, C, NVOX]
{
    __shared__ float smax[NC * NVOX];   // [ch][vox] 32000 B (matches out layout)
    __shared__ int   slist[LCAP];       // packed (vid<<13)|p
    __shared__ int   scnt;

    const int br  = blockIdx.x;         // 0 .. B*R-1
    const int b   = br / NR;
    const int tid = threadIdx.x;

    // ROI params (uniform across CTA)
    const float* roi = rois + br * 7;
    const float cx = roi[0];
    const float cy = roi[1];
    const float dz = roi[5];
    const float cz = roi[2] + 0.5f * dz;       // geometric z center
    const float dx = roi[3];
    const float dy = roi[4];
    const float ry = roi[6];
    const float cosr = cosf(ry), sinr = sinf(ry);
    const float hx = 0.5f * dx, hy = 0.5f * dy, hz = 0.5f * dz;
    const float vx = __fdiv_rn(dx, (float)OUTD);
    const float vy = __fdiv_rn(dy, (float)OUTD);
    const float vz = __fdiv_rn(dz, (float)OUTD);

    // init smax to -FLT_MAX (vectorized), scnt to 0
    {
        float4* s4 = (float4*)smax;
        const float4 neg = make_float4(-FLT_MAX, -FLT_MAX, -FLT_MAX, -FLT_MAX);
        #pragma unroll
        for (int i = tid; i < NC * NVOX / 4; i += NT) s4[i] = neg;
        if (tid == 0) scnt = 0;
    }

    const float* ptsb = pts + (size_t)b * NP * 3;

    // hoist all point loads: 24 independent LDGs -> latency exposed once
    float px[PPT], py[PPT], pz[PPT];
    #pragma unroll
    for (int k = 0; k < PPT; k++) {
        const int p = k * NT + tid;
        px[k] = ptsb[p * 3 + 0];
        py[k] = ptsb[p * 3 + 1];
        pz[k] = ptsb[p * 3 + 2];
    }
    __syncthreads();   // smax init + scnt visible

    // classify all points, push inside ones to the list
    #pragma unroll
    for (int k = 0; k < PPT; k++) {
        const int p = k * NT + tid;
        const float sx = px[k] - cx;
        const float sy = py[k] - cy;
        const float lz = pz[k] - cz;
        const float lx =  sx * cosr + sy * sinr;   // rotate world -> box (-ry)
        const float ly = -sx * sinr + sy * cosr;

        if (fabsf(lx) < hx && fabsf(ly) < hy && fabsf(lz) < hz) {
            int ix = (int)floorf(__fdiv_rn(lx + hx, vx));
            int iy = (int)floorf(__fdiv_rn(ly + hy, vy));
            int iz = (int)floorf(__fdiv_rn(lz + hz, vz));
            ix = min(max(ix, 0), OUTD - 1);
            iy = min(max(iy, 0), OUTD - 1);
            iz = min(max(iz, 0), OUTD - 1);
            const int vid = (ix * OUTD + iy) * OUTD + iz;
            const int slot = atomicAdd(&scnt, 1);
            if (slot < LCAP) slist[slot] = (vid << 13) | p;
        }
    }
    __syncthreads();

    // cooperative gather from transposed features: one float4 (=4 channels)
    // per (pair, quarter) job -> contiguous 256B per point, ~8 lines/warp
    const int n = min(scnt, LCAP);
    const float4* tf4 = (const float4*)(g_tf + (size_t)b * NP * NC);
    for (int i = tid; i < n * 16; i += NT) {
        const int pair = slist[i >> 4];
        const int q    = i & 15;
        const int pp   = pair & (NP - 1);
        const int vid  = pair >> 13;
        const float4 v = __ldg(tf4 + (size_t)pp * 16 + q);
        const int c0   = q * 4;
        atomicMaxFloat(&smax[(c0 + 0) * NVOX + vid], v.x);
        atomicMaxFloat(&smax[(c0 + 1) * NVOX + vid], v.y);
        atomicMaxFloat(&smax[(c0 + 2) * NVOX + vid], v.z);
        atomicMaxFloat(&smax[(c0 + 3) * NVOX + vid], v.w);
    }
    __syncthreads();

    // vectorized write out [C, NVOX]; empty voxel (still -FLT_MAX) -> 0
    float4*       o4 = (float4*)(out + (size_t)br * NC * NVOX);
    const float4* s4 = (const float4*)smax;
    #pragma unroll
    for (int i = tid; i < NC * NVOX / 4; i += NT) {
        float4 m = s4[i];
        m.x = (m.x == -FLT_MAX) ? 0.0f : m.x;
        m.y = (m.y == -FLT_MAX) ? 0.0f : m.y;
        m.z = (m.z == -FLT_MAX) ? 0.0f : m.z;
        m.w = (m.w == -FLT_MAX) ? 0.0f : m.w;
        o4[i] = m;
    }
}

extern "C" void kernel_launch(void* const* d_in, const int* in_sizes, int n_in,
                              void* d_out, int out_size) {
    const float* pts   = (const float*)d_in[0];  // points_xyz [B,P,3]
    const float* feats = (const float*)d_in[1];  // features   [B,C,P]
    const float* rois  = (const float*)d_in[2];  // rois       [B,R,7]
    float* out = (float*)d_out;                  // [B*R, C, NVOX]

    dim3 tg(NP / 32, NC / 32, NB);               // 256 x 2 x 2 = 1024 blocks
    transpose_kernel<<<tg, 256>>>(feats);
    roipool3d_kernel<<<NB * NR, NT>>>(pts, rois, out);
}